// round 9
// baseline (speedup 1.0000x reference)
#include <cuda_runtime.h>

#define D_CH 20
#define GV 128
#define NUM_EMB (GV * GV * GV)
#define XCH 8                           // gx / 16
#define NUM_BINS (GV * GV * XCH)        // 131072
#define MAXP (1 << 21)
#define SCAN_BLOCKS 512                 // 512 blocks x 256 = 131072

__device__ int    g_hist[NUM_BINS];
__device__ int    g_base[NUM_BINS];
__device__ int    g_blocksum[SCAN_BLOCKS];
__device__ float4 g_tmp[MAXP];          // (x,y,z, rank-bits)
__device__ float4 g_sorted[MAXP];       // (x,y,z, orig-bits)

// spread low 7 bits of v to even bit positions
__device__ __forceinline__ unsigned spread7(unsigned v)
{
    v &= 0x7Fu;
    v = (v | (v << 8)) & 0x00FF00FFu;
    v = (v | (v << 4)) & 0x0F0F0F0Fu;
    v = (v | (v << 2)) & 0x33333333u;
    v = (v | (v << 1)) & 0x55555555u;
    return v;
}

// Morton-ordered (gy,gz) patch index, x-chunk minor: compact 3D sweep.
__device__ __forceinline__ int bin_of(float px, float py, float pz)
{
    int gx = (int)floorf((px + 1.0f) * 0.5f * (float)GV);
    int gy = (int)floorf((py + 1.0f) * 0.5f * (float)GV);
    int gz = (int)floorf((pz + 1.0f) * 0.5f * (float)GV);
    gx = min(max(gx, 0), GV - 1);
    gy = min(max(gy, 0), GV - 1);
    gz = min(max(gz, 0), GV - 1);
    unsigned m = spread7((unsigned)gy) | (spread7((unsigned)gz) << 1);
    return (int)(m * XCH) + (gx >> 4);
}

__global__ void zero_kernel()
{
    int i = blockIdx.x * blockDim.x + threadIdx.x;
    if (i < NUM_BINS) g_hist[i] = 0;
}

// Pass 1 (4 pts/thread): count + per-point rank, stash point+rank in L2 temp.
__global__ void hist_rank_kernel(const float* __restrict__ x, int n)
{
    int p0 = (blockIdx.x * blockDim.x + threadIdx.x) * 4;
    if (p0 >= n) return;

    if (p0 + 4 <= n) {
        // 12 floats = 3 aligned float4 loads (p0 % 4 == 0 -> p0*3 % 4 == 0)
        const float4* x4 = (const float4*)(x + (size_t)p0 * 3);
        float4 a = __ldg(&x4[0]);
        float4 b = __ldg(&x4[1]);
        float4 c = __ldg(&x4[2]);
        float pxs[4] = { a.x, a.w, b.z, c.y };
        float pys[4] = { a.y, b.x, b.w, c.z };
        float pzs[4] = { a.z, b.y, c.x, c.w };
        int bins[4];
        #pragma unroll
        for (int i = 0; i < 4; i++)
            bins[i] = bin_of(pxs[i], pys[i], pzs[i]);
        int ranks[4];
        #pragma unroll
        for (int i = 0; i < 4; i++)
            ranks[i] = atomicAdd(&g_hist[bins[i]], 1);
        #pragma unroll
        for (int i = 0; i < 4; i++)
            g_tmp[p0 + i] = make_float4(pxs[i], pys[i], pzs[i],
                                        __int_as_float(ranks[i]));
    } else {
        for (int p = p0; p < n; p++) {
            float px = __ldg(&x[p * 3 + 0]);
            float py = __ldg(&x[p * 3 + 1]);
            float pz = __ldg(&x[p * 3 + 2]);
            int bin  = bin_of(px, py, pz);
            int rank = atomicAdd(&g_hist[bin], 1);
            g_tmp[p] = make_float4(px, py, pz, __int_as_float(rank));
        }
    }
}

// Scan stage A: per-block sums of 256 bins.
__global__ void scanA_kernel()
{
    __shared__ int sh[256];
    int i = blockIdx.x * 256 + threadIdx.x;
    sh[threadIdx.x] = g_hist[i];
    __syncthreads();
    for (int off = 128; off > 0; off >>= 1) {
        if (threadIdx.x < off) sh[threadIdx.x] += sh[threadIdx.x + off];
        __syncthreads();
    }
    if (threadIdx.x == 0) g_blocksum[blockIdx.x] = sh[0];
}

// Scan stage C (B folded in): each block reduces blocksums[0..blockIdx) itself,
// then scans its 256 bins.
__global__ void scanC_kernel()
{
    __shared__ int sred[256];
    __shared__ int sh[256];
    const int tid = threadIdx.x;
    const int b   = blockIdx.x;

    int s0 = (tid       < b) ? g_blocksum[tid]       : 0;
    int s1 = (tid + 256 < b) ? g_blocksum[tid + 256] : 0;
    sred[tid] = s0 + s1;

    int i = b * 256 + tid;
    int v = g_hist[i];
    sh[tid] = v;
    __syncthreads();

    for (int off = 128; off > 0; off >>= 1) {
        if (tid < off) sred[tid] += sred[tid + off];
        __syncthreads();
    }
    int blockbase = sred[0];
    __syncthreads();

    // inclusive Hillis-Steele over this block's 256 bins
    for (int off = 1; off < 256; off <<= 1) {
        int a = sh[tid];
        int add = (tid >= off) ? sh[tid - off] : 0;
        __syncthreads();
        sh[tid] = a + add;
        __syncthreads();
    }
    g_base[i] = (sh[tid] - v) + blockbase;
}

// Pass 2 (4 pts/thread): atomic-free scatter, pos = base[bin] + rank.
__global__ void scatter_kernel(int n)
{
    int p0 = (blockIdx.x * blockDim.x + threadIdx.x) * 4;
    if (p0 >= n) return;
    int cnt = min(4, n - p0);
    #pragma unroll 4
    for (int i = 0; i < cnt; i++) {
        float4 t = g_tmp[p0 + i];
        int bin  = bin_of(t.x, t.y, t.z);
        int pos  = g_base[bin] + __float_as_int(t.w);
        g_sorted[pos] = make_float4(t.x, t.y, t.z, __int_as_float(p0 + i));
    }
}

__device__ __forceinline__ void interp_point(
    const float* __restrict__ grid, float* __restrict__ out,
    float px, float py, float pz, int orig, unsigned int c4)
{
    unsigned int cbase = c4 * 4u;

    int gx = (int)floorf((px + 1.0f) * 0.5f * (float)GV);
    int gy = (int)floorf((py + 1.0f) * 0.5f * (float)GV);
    int gz = (int)floorf((pz + 1.0f) * 0.5f * (float)GV);

    const float inv_v2 = 2.0f / (float)GV;   // exact in fp32
    float x1 = (float)gx * inv_v2 - 1.0f;
    float x2 = (float)(gx + 1) * inv_v2 - 1.0f;
    float y1 = (float)gy * inv_v2 - 1.0f;
    float y2 = (float)(gy + 1) * inv_v2 - 1.0f;
    float z1 = (float)gz * inv_v2 - 1.0f;
    float z2 = (float)(gz + 1) * inv_v2 - 1.0f;

    const float inv_den = 64.0f;             // 1/(2/128), exact
    float wx0 = (x2 - px) * inv_den;
    float wx1 = (px - x1) * inv_den;
    float wy0 = (y2 - py) * inv_den;
    float wy1 = (py - y1) * inv_den;
    float wz0 = (z2 - pz) * inv_den;
    float wz1 = (pz - z1) * inv_den;

    int base = gx + gy * GV + gz * GV * GV;
    const int maxi = NUM_EMB - 1;
    int f000 = min(base,                  maxi);
    int f100 = min(base + 1,              maxi);
    int f010 = min(base + GV,             maxi);
    int f110 = min(base + GV + 1,         maxi);
    int f001 = min(base + GV*GV,          maxi);
    int f101 = min(base + GV*GV + 1,      maxi);
    int f011 = min(base + GV*GV + GV,     maxi);
    int f111 = min(base + GV*GV + GV + 1, maxi);

    const float4* g4 = (const float4*)grid;
    float4 q000 = __ldg(&g4[((size_t)f000 * D_CH + cbase) >> 2]);
    float4 q100 = __ldg(&g4[((size_t)f100 * D_CH + cbase) >> 2]);
    float4 q010 = __ldg(&g4[((size_t)f010 * D_CH + cbase) >> 2]);
    float4 q110 = __ldg(&g4[((size_t)f110 * D_CH + cbase) >> 2]);
    float4 q001 = __ldg(&g4[((size_t)f001 * D_CH + cbase) >> 2]);
    float4 q101 = __ldg(&g4[((size_t)f101 * D_CH + cbase) >> 2]);
    float4 q011 = __ldg(&g4[((size_t)f011 * D_CH + cbase) >> 2]);
    float4 q111 = __ldg(&g4[((size_t)f111 * D_CH + cbase) >> 2]);

    float4 r;
    {
        float fx0 = wx0 * q000.x + wx1 * q100.x;
        float fx1 = wx0 * q010.x + wx1 * q110.x;
        float fx2 = wx0 * q001.x + wx1 * q101.x;
        float fx3 = wx0 * q011.x + wx1 * q111.x;
        r.x = wz0 * (wy0 * fx0 + wy1 * fx1) + wz1 * (wy0 * fx2 + wy1 * fx3);
    }
    {
        float fx0 = wx0 * q000.y + wx1 * q100.y;
        float fx1 = wx0 * q010.y + wx1 * q110.y;
        float fx2 = wx0 * q001.y + wx1 * q101.y;
        float fx3 = wx0 * q011.y + wx1 * q111.y;
        r.y = wz0 * (wy0 * fx0 + wy1 * fx1) + wz1 * (wy0 * fx2 + wy1 * fx3);
    }
    {
        float fx0 = wx0 * q000.z + wx1 * q100.z;
        float fx1 = wx0 * q010.z + wx1 * q110.z;
        float fx2 = wx0 * q001.z + wx1 * q101.z;
        float fx3 = wx0 * q011.z + wx1 * q111.z;
        r.z = wz0 * (wy0 * fx0 + wy1 * fx1) + wz1 * (wy0 * fx2 + wy1 * fx3);
    }
    {
        float fx0 = wx0 * q000.w + wx1 * q100.w;
        float fx1 = wx0 * q010.w + wx1 * q110.w;
        float fx2 = wx0 * q001.w + wx1 * q101.w;
        float fx3 = wx0 * q011.w + wx1 * q111.w;
        r.w = wz0 * (wy0 * fx0 + wy1 * fx1) + wz1 * (wy0 * fx2 + wy1 * fx3);
    }

    __stcs((float4*)out + (size_t)orig * 5u + c4, r);
}

// Gather in Morton-sorted order: 5 threads/point, dense.
__global__ void __launch_bounds__(256) gather_kernel(
    const float* __restrict__ grid,
    float* __restrict__ out,
    int n_pts)
{
    unsigned int gid = blockIdx.x * 256u + threadIdx.x;
    unsigned int total = (unsigned int)n_pts * 5u;
    if (gid >= total) return;

    unsigned int sp = gid / 5u;
    unsigned int c4 = gid - sp * 5u;

    float4 pt = __ldg(&g_sorted[sp]);     // L2-resident (written by scatter)
    interp_point(grid, out, pt.x, pt.y, pt.z, __float_as_int(pt.w), c4);
}

// Fallback (unsorted) path if n_pts exceeds static scratch capacity.
__global__ void __launch_bounds__(256) gather_direct_kernel(
    const float* __restrict__ x,
    const float* __restrict__ grid,
    float* __restrict__ out,
    int n_pts)
{
    unsigned int gid = blockIdx.x * 256u + threadIdx.x;
    unsigned int total = (unsigned int)n_pts * 5u;
    if (gid >= total) return;
    unsigned int p = gid / 5u;
    unsigned int c4 = gid - p * 5u;
    float px = __ldg(&x[p * 3 + 0]);
    float py = __ldg(&x[p * 3 + 1]);
    float pz = __ldg(&x[p * 3 + 2]);
    interp_point(grid, out, px, py, pz, (int)p, c4);
}

extern "C" void kernel_launch(void* const* d_in, const int* in_sizes, int n_in,
                              void* d_out, int out_size)
{
    const float* x    = (const float*)d_in[0];
    const float* grid = (const float*)d_in[1];
    float* out        = (float*)d_out;

    int n_pts = in_sizes[0] / 3;

    if (n_pts > MAXP) {
        unsigned int total = (unsigned int)n_pts * 5u;
        gather_direct_kernel<<<(total + 255u) / 256u, 256>>>(x, grid, out, n_pts);
        return;
    }

    int pb4 = (n_pts + 1023) / 1024;       // 4 points per thread
    unsigned int total = (unsigned int)n_pts * 5u;

    zero_kernel<<<(NUM_BINS + 1023) / 1024, 1024>>>();
    hist_rank_kernel<<<pb4, 256>>>(x, n_pts);
    scanA_kernel<<<SCAN_BLOCKS, 256>>>();
    scanC_kernel<<<SCAN_BLOCKS, 256>>>();
    scatter_kernel<<<pb4, 256>>>(n_pts);
    gather_kernel<<<(total + 255u) / 256u, 256>>>(grid, out, n_pts);
}

// round 11
// speedup vs baseline: 1.2864x; 1.2864x over previous
#include <cuda_runtime.h>

#define D_CH 20
#define GV 128
#define NUM_EMB (GV * GV * GV)
#define XCH 8                           // gx / 16
#define NUM_BINS (GV * GV * XCH)        // 131072
#define MAXP (1 << 21)
#define SCAN_BLOCKS 512                 // 512 blocks x 256 = 131072

__device__ int    g_hist[NUM_BINS];
__device__ int    g_base[NUM_BINS];
__device__ int    g_blocksum[SCAN_BLOCKS];
__device__ float4 g_tmp[MAXP];          // (x,y,z, rank-bits)
__device__ float4 g_sorted[MAXP];       // (x,y,z, orig-bits)

// Linear bin key: (gz, gy) major, x-chunk minor -> near-sequential grid sweep.
__device__ __forceinline__ int bin_of(float px, float py, float pz)
{
    int gx = (int)floorf((px + 1.0f) * 0.5f * (float)GV);
    int gy = (int)floorf((py + 1.0f) * 0.5f * (float)GV);
    int gz = (int)floorf((pz + 1.0f) * 0.5f * (float)GV);
    gx = min(max(gx, 0), GV - 1);
    gy = min(max(gy, 0), GV - 1);
    gz = min(max(gz, 0), GV - 1);
    return ((gz * GV + gy) * XCH) + (gx >> 4);
}

__global__ void zero_kernel()
{
    int i = blockIdx.x * blockDim.x + threadIdx.x;
    if (i < NUM_BINS) g_hist[i] = 0;
}

// Pass 1 (4 pts/thread): count + per-point rank, stash point+rank in L2 temp.
__global__ void hist_rank_kernel(const float* __restrict__ x, int n)
{
    int p0 = (blockIdx.x * blockDim.x + threadIdx.x) * 4;
    if (p0 >= n) return;

    if (p0 + 4 <= n) {
        const float4* x4 = (const float4*)(x + (size_t)p0 * 3);
        float4 a = __ldg(&x4[0]);
        float4 b = __ldg(&x4[1]);
        float4 c = __ldg(&x4[2]);
        float pxs[4] = { a.x, a.w, b.z, c.y };
        float pys[4] = { a.y, b.x, b.w, c.z };
        float pzs[4] = { a.z, b.y, c.x, c.w };
        int bins[4];
        #pragma unroll
        for (int i = 0; i < 4; i++)
            bins[i] = bin_of(pxs[i], pys[i], pzs[i]);
        int ranks[4];
        #pragma unroll
        for (int i = 0; i < 4; i++)
            ranks[i] = atomicAdd(&g_hist[bins[i]], 1);
        #pragma unroll
        for (int i = 0; i < 4; i++)
            g_tmp[p0 + i] = make_float4(pxs[i], pys[i], pzs[i],
                                        __int_as_float(ranks[i]));
    } else {
        for (int p = p0; p < n; p++) {
            float px = __ldg(&x[p * 3 + 0]);
            float py = __ldg(&x[p * 3 + 1]);
            float pz = __ldg(&x[p * 3 + 2]);
            int bin  = bin_of(px, py, pz);
            int rank = atomicAdd(&g_hist[bin], 1);
            g_tmp[p] = make_float4(px, py, pz, __int_as_float(rank));
        }
    }
}

// Scan stage A: per-block sums of 256 bins (warp intrinsics, 1 barrier).
__global__ void scanA_kernel()
{
    __shared__ int wsum[8];
    int tid = threadIdx.x;
    int v = g_hist[blockIdx.x * 256 + tid];
    int ws = __reduce_add_sync(0xFFFFFFFFu, v);
    if ((tid & 31) == 0) wsum[tid >> 5] = ws;
    __syncthreads();
    if (tid < 32) {
        int s = (tid < 8) ? wsum[tid] : 0;
        s = __reduce_add_sync(0xFFFFFFFFu, s);
        if (tid == 0) g_blocksum[blockIdx.x] = s;
    }
}

// Scan stage C (B folded in): block base = sum(blocksums[0..b)), then
// warp-shuffle exclusive scan of this block's 256 bins.
__global__ void scanC_kernel()
{
    __shared__ int wsum[8];      // per-warp scan sums
    __shared__ int bsum[8];      // block-base partial sums
    const int tid  = threadIdx.x;
    const int lane = tid & 31;
    const int wrp  = tid >> 5;
    const int b    = blockIdx.x;

    // ---- block base: reduce blocksums[0..b) (512 entries, 2 per thread)
    int s0 = (tid       < b) ? g_blocksum[tid]       : 0;
    int s1 = (tid + 256 < b) ? g_blocksum[tid + 256] : 0;
    int bs = __reduce_add_sync(0xFFFFFFFFu, s0 + s1);
    if (lane == 0) bsum[wrp] = bs;

    // ---- per-warp inclusive scan of this block's bins
    int i = b * 256 + tid;
    int v = g_hist[i];
    int incl = v;
    #pragma unroll
    for (int off = 1; off < 32; off <<= 1) {
        int t = __shfl_up_sync(0xFFFFFFFFu, incl, off);
        if (lane >= off) incl += t;
    }
    if (lane == 31) wsum[wrp] = incl;
    __syncthreads();

    int blockbase = 0;
    {
        // serial-ish accumulation over 8 warp sums + 8 base partials (tiny)
        #pragma unroll
        for (int w = 0; w < 8; w++) {
            blockbase += bsum[w];
            if (w < wrp) blockbase += wsum[w];
        }
    }
    g_base[i] = blockbase + (incl - v);
}

// Pass 2 (4 pts/thread): atomic-free scatter, pos = base[bin] + rank.
__global__ void scatter_kernel(int n)
{
    int p0 = (blockIdx.x * blockDim.x + threadIdx.x) * 4;
    if (p0 >= n) return;
    int cnt = min(4, n - p0);
    #pragma unroll 4
    for (int i = 0; i < cnt; i++) {
        float4 t = g_tmp[p0 + i];
        int bin  = bin_of(t.x, t.y, t.z);
        int pos  = g_base[bin] + __float_as_int(t.w);
        g_sorted[pos] = make_float4(t.x, t.y, t.z, __int_as_float(p0 + i));
    }
}

__device__ __forceinline__ void interp_point(
    const float* __restrict__ grid, float* __restrict__ out,
    float px, float py, float pz, int orig, unsigned int c4)
{
    unsigned int cbase = c4 * 4u;

    int gx = (int)floorf((px + 1.0f) * 0.5f * (float)GV);
    int gy = (int)floorf((py + 1.0f) * 0.5f * (float)GV);
    int gz = (int)floorf((pz + 1.0f) * 0.5f * (float)GV);

    const float inv_v2 = 2.0f / (float)GV;   // exact in fp32
    float x1 = (float)gx * inv_v2 - 1.0f;
    float x2 = (float)(gx + 1) * inv_v2 - 1.0f;
    float y1 = (float)gy * inv_v2 - 1.0f;
    float y2 = (float)(gy + 1) * inv_v2 - 1.0f;
    float z1 = (float)gz * inv_v2 - 1.0f;
    float z2 = (float)(gz + 1) * inv_v2 - 1.0f;

    const float inv_den = 64.0f;             // 1/(2/128), exact
    float wx0 = (x2 - px) * inv_den;
    float wx1 = (px - x1) * inv_den;
    float wy0 = (y2 - py) * inv_den;
    float wy1 = (py - y1) * inv_den;
    float wz0 = (z2 - pz) * inv_den;
    float wz1 = (pz - z1) * inv_den;

    int base = gx + gy * GV + gz * GV * GV;
    const int maxi = NUM_EMB - 1;
    int f000 = min(base,                  maxi);
    int f100 = min(base + 1,              maxi);
    int f010 = min(base + GV,             maxi);
    int f110 = min(base + GV + 1,         maxi);
    int f001 = min(base + GV*GV,          maxi);
    int f101 = min(base + GV*GV + 1,      maxi);
    int f011 = min(base + GV*GV + GV,     maxi);
    int f111 = min(base + GV*GV + GV + 1, maxi);

    const float4* g4 = (const float4*)grid;
    float4 q000 = __ldg(&g4[((size_t)f000 * D_CH + cbase) >> 2]);
    float4 q100 = __ldg(&g4[((size_t)f100 * D_CH + cbase) >> 2]);
    float4 q010 = __ldg(&g4[((size_t)f010 * D_CH + cbase) >> 2]);
    float4 q110 = __ldg(&g4[((size_t)f110 * D_CH + cbase) >> 2]);
    float4 q001 = __ldg(&g4[((size_t)f001 * D_CH + cbase) >> 2]);
    float4 q101 = __ldg(&g4[((size_t)f101 * D_CH + cbase) >> 2]);
    float4 q011 = __ldg(&g4[((size_t)f011 * D_CH + cbase) >> 2]);
    float4 q111 = __ldg(&g4[((size_t)f111 * D_CH + cbase) >> 2]);

    float4 r;
    {
        float fx0 = wx0 * q000.x + wx1 * q100.x;
        float fx1 = wx0 * q010.x + wx1 * q110.x;
        float fx2 = wx0 * q001.x + wx1 * q101.x;
        float fx3 = wx0 * q011.x + wx1 * q111.x;
        r.x = wz0 * (wy0 * fx0 + wy1 * fx1) + wz1 * (wy0 * fx2 + wy1 * fx3);
    }
    {
        float fx0 = wx0 * q000.y + wx1 * q100.y;
        float fx1 = wx0 * q010.y + wx1 * q110.y;
        float fx2 = wx0 * q001.y + wx1 * q101.y;
        float fx3 = wx0 * q011.y + wx1 * q111.y;
        r.y = wz0 * (wy0 * fx0 + wy1 * fx1) + wz1 * (wy0 * fx2 + wy1 * fx3);
    }
    {
        float fx0 = wx0 * q000.z + wx1 * q100.z;
        float fx1 = wx0 * q010.z + wx1 * q110.z;
        float fx2 = wx0 * q001.z + wx1 * q101.z;
        float fx3 = wx0 * q011.z + wx1 * q111.z;
        r.z = wz0 * (wy0 * fx0 + wy1 * fx1) + wz1 * (wy0 * fx2 + wy1 * fx3);
    }
    {
        float fx0 = wx0 * q000.w + wx1 * q100.w;
        float fx1 = wx0 * q010.w + wx1 * q110.w;
        float fx2 = wx0 * q001.w + wx1 * q101.w;
        float fx3 = wx0 * q011.w + wx1 * q111.w;
        r.w = wz0 * (wy0 * fx0 + wy1 * fx1) + wz1 * (wy0 * fx2 + wy1 * fx3);
    }

    __stcs((float4*)out + (size_t)orig * 5u + c4, r);
}

// Gather in sorted (gz, gy, x-chunk) order: 5 threads/point, dense.
__global__ void __launch_bounds__(256) gather_kernel(
    const float* __restrict__ grid,
    float* __restrict__ out,
    int n_pts)
{
    unsigned int gid = blockIdx.x * 256u + threadIdx.x;
    unsigned int total = (unsigned int)n_pts * 5u;
    if (gid >= total) return;

    unsigned int sp = gid / 5u;
    unsigned int c4 = gid - sp * 5u;

    float4 pt = __ldg(&g_sorted[sp]);     // L2-resident (written by scatter)
    interp_point(grid, out, pt.x, pt.y, pt.z, __float_as_int(pt.w), c4);
}

// Fallback (unsorted) path if n_pts exceeds static scratch capacity.
__global__ void __launch_bounds__(256) gather_direct_kernel(
    const float* __restrict__ x,
    const float* __restrict__ grid,
    float* __restrict__ out,
    int n_pts)
{
    unsigned int gid = blockIdx.x * 256u + threadIdx.x;
    unsigned int total = (unsigned int)n_pts * 5u;
    if (gid >= total) return;
    unsigned int p = gid / 5u;
    unsigned int c4 = gid - p * 5u;
    float px = __ldg(&x[p * 3 + 0]);
    float py = __ldg(&x[p * 3 + 1]);
    float pz = __ldg(&x[p * 3 + 2]);
    interp_point(grid, out, px, py, pz, (int)p, c4);
}

extern "C" void kernel_launch(void* const* d_in, const int* in_sizes, int n_in,
                              void* d_out, int out_size)
{
    const float* x    = (const float*)d_in[0];
    const float* grid = (const float*)d_in[1];
    float* out        = (float*)d_out;

    int n_pts = in_sizes[0] / 3;

    if (n_pts > MAXP) {
        unsigned int total = (unsigned int)n_pts * 5u;
        gather_direct_kernel<<<(total + 255u) / 256u, 256>>>(x, grid, out, n_pts);
        return;
    }

    int pb4 = (n_pts + 1023) / 1024;       // 4 points per thread
    unsigned int total = (unsigned int)n_pts * 5u;

    zero_kernel<<<(NUM_BINS + 1023) / 1024, 1024>>>();
    hist_rank_kernel<<<pb4, 256>>>(x, n_pts);
    scanA_kernel<<<SCAN_BLOCKS, 256>>>();
    scanC_kernel<<<SCAN_BLOCKS, 256>>>();
    scatter_kernel<<<pb4, 256>>>(n_pts);
    gather_kernel<<<(total + 255u) / 256u, 256>>>(grid, out, n_pts);
}